// round 1
// baseline (speedup 1.0000x reference)
#include <cuda_runtime.h>

// Shapes fixed by the problem: B=64, L=512, E=64, H=8, D=8
#define LSEQ 512
#define EDIM 64

// Scratch (static device globals — no allocation)
__device__ float g_qh[64 * 512 * 64];
__device__ float g_kh[64 * 512 * 64];
__device__ float g_vh[64 * 512 * 64];
__device__ float g_ctx[64 * 512 * 64];

// ---------------------------------------------------------------------------
// Projection: out[r][c] = sum_d x[r][d] * W[c][d] + bias[c]   (x @ W.T + b)
// Block: 256 threads, 16 rows. W transposed into padded SMEM (conflict-free).
// ---------------------------------------------------------------------------
__global__ __launch_bounds__(256) void proj_kernel(
    const float* __restrict__ x, const float* __restrict__ W,
    const float* __restrict__ bias, float* __restrict__ out) {
  __shared__ float WT[64 * 65];
  __shared__ float xs[16 * 64];
  int tid = threadIdx.x;
  int row0 = blockIdx.x * 16;

  #pragma unroll
  for (int idx = tid; idx < 4096; idx += 256) {
    int c = idx >> 6, d = idx & 63;
    WT[d * 65 + c] = W[idx];
  }
  #pragma unroll
  for (int idx = tid; idx < 1024; idx += 256)
    xs[idx] = x[row0 * 64 + idx];
  __syncthreads();

  int c = tid & 63, s = tid >> 6;  // col, row-slot (rows s, s+4, s+8, s+12)
  float a0 = 0.f, a1 = 0.f, a2 = 0.f, a3 = 0.f;
  #pragma unroll
  for (int d = 0; d < 64; d++) {
    float w = WT[d * 65 + c];
    a0 = fmaf(xs[(s) * 64 + d], w, a0);
    a1 = fmaf(xs[(s + 4) * 64 + d], w, a1);
    a2 = fmaf(xs[(s + 8) * 64 + d], w, a2);
    a3 = fmaf(xs[(s + 12) * 64 + d], w, a3);
  }
  float bc = bias[c];
  out[(row0 + s) * 64 + c] = a0 + bc;
  out[(row0 + s + 4) * 64 + c] = a1 + bc;
  out[(row0 + s + 8) * 64 + c] = a2 + bc;
  out[(row0 + s + 12) * 64 + c] = a3 + bc;
}

// ---------------------------------------------------------------------------
// Attention: block = (query-tile of 32, batch). 256 threads = 8 warps.
// Warp qg owns queries qg*4..qg*4+3 across ALL 512 keys (lane = key phase),
// so softmax + ctx reductions are warp shuffles only.
// Per head: stage K,V transposed [8][512] in SMEM; accumulate head-mean
// attention into a [32][512] SMEM tile; write ctx per head.
// ---------------------------------------------------------------------------
__global__ __launch_bounds__(256) void attn_kernel(
    const float* __restrict__ qh, const float* __restrict__ kh,
    const float* __restrict__ vh, float* __restrict__ ctx,
    float* __restrict__ attn_out) {
  extern __shared__ float sm[];
  float* Ks = sm;            // [8][512]
  float* Vs = sm + 4096;     // [8][512]
  float* Aacc = sm + 8192;   // [32][512]

  int b = blockIdx.y;
  int q0 = blockIdx.x * 32;
  int tid = threadIdx.x;
  int qg = tid >> 5;   // warp id = query group
  int ks = tid & 31;   // lane = key phase

  for (int i = tid; i < 32 * 512; i += 256) Aacc[i] = 0.f;

  const float scale = 0.3535533905932738f;  // 1/sqrt(8)
  const float* kbase = kh + (size_t)b * 512 * 64;
  const float* vbase = vh + (size_t)b * 512 * 64;

  #pragma unroll 1
  for (int h = 0; h < 8; h++) {
    __syncthreads();  // prior head done with Ks/Vs (and Aacc zero visible)
    for (int idx = tid; idx < 4096; idx += 256) {
      int m = idx >> 3, d = idx & 7;
      int g = m * 64 + h * 8 + d;
      Ks[d * 512 + m] = kbase[g];
      Vs[d * 512 + m] = vbase[g];
    }
    __syncthreads();

    // queries for this warp, this head (pre-scaled)
    float qr[4][8];
    #pragma unroll
    for (int i = 0; i < 4; i++) {
      const float* qp = qh + ((size_t)(b * 512 + q0 + qg * 4 + i)) * 64 + h * 8;
      #pragma unroll
      for (int d = 0; d < 8; d++) qr[i][d] = qp[d] * scale;
    }

    // scores: 4 queries x 16 key-chunks (key m = ks + 32*j)
    float s[4][16];
    #pragma unroll
    for (int i = 0; i < 4; i++)
      #pragma unroll
      for (int j = 0; j < 16; j++) s[i][j] = 0.f;

    #pragma unroll
    for (int j = 0; j < 16; j++) {
      int m = ks + 32 * j;
      #pragma unroll
      for (int d = 0; d < 8; d++) {
        float kv = Ks[d * 512 + m];
        #pragma unroll
        for (int i = 0; i < 4; i++) s[i][j] = fmaf(qr[i][d], kv, s[i][j]);
      }
    }

    float cacc[4][8];
    #pragma unroll
    for (int i = 0; i < 4; i++)
      #pragma unroll
      for (int d = 0; d < 8; d++) cacc[i][d] = 0.f;

    #pragma unroll
    for (int i = 0; i < 4; i++) {
      // softmax over 512 keys: warp-wide (lanes cover key space)
      float M = s[i][0];
      #pragma unroll
      for (int j = 1; j < 16; j++) M = fmaxf(M, s[i][j]);
      #pragma unroll
      for (int off = 16; off; off >>= 1)
        M = fmaxf(M, __shfl_xor_sync(0xffffffffu, M, off));
      float Z = 0.f;
      #pragma unroll
      for (int j = 0; j < 16; j++) {
        float e = __expf(s[i][j] - M);
        s[i][j] = e;
        Z += e;
      }
      #pragma unroll
      for (int off = 16; off; off >>= 1)
        Z += __shfl_xor_sync(0xffffffffu, Z, off);
      float inv = 1.0f / Z;

      #pragma unroll
      for (int j = 0; j < 16; j++) {
        float p = s[i][j] * inv;
        int m = ks + 32 * j;
        Aacc[(qg * 4 + i) * 512 + m] += 0.125f * p;  // head mean
        #pragma unroll
        for (int d = 0; d < 8; d++)
          cacc[i][d] = fmaf(p, Vs[d * 512 + m], cacc[i][d]);
      }
    }

    // warp-reduce ctx partials; every lane ends with all 32 totals
    #pragma unroll
    for (int i = 0; i < 4; i++)
      #pragma unroll
      for (int d = 0; d < 8; d++)
        #pragma unroll
        for (int off = 16; off; off >>= 1)
          cacc[i][d] += __shfl_xor_sync(0xffffffffu, cacc[i][d], off);

    // lane ks writes entry (i = ks>>3, d = ks&7) — static select chain
    int li = ks >> 3, ld = ks & 7;
    float val = 0.f;
    #pragma unroll
    for (int i = 0; i < 4; i++)
      #pragma unroll
      for (int d = 0; d < 8; d++)
        if (li == i && ld == d) val = cacc[i][d];
    ctx[((size_t)(b * 512 + q0 + qg * 4 + li)) * 64 + h * 8 + ld] = val;
  }

  __syncthreads();
  // write head-averaged attention, coalesced
  for (int idx = tid; idx < 32 * 512; idx += 256) {
    int q = idx >> 9, m = idx & 511;
    attn_out[((size_t)b * 512 + q0 + q) * 512 + m] = Aacc[idx];
  }
}

// ---------------------------------------------------------------------------
// Epilogue: o = ctx@Wo.T + bo + prev; x = LN1(o);
//           f = relu(x@W1.T + b1)@W2.T + b2 + x; out = LN2(f)
// Block: 256 threads = 64 cols x 4 row-slots; 64 rows/block (16 groups).
// ---------------------------------------------------------------------------
__global__ __launch_bounds__(256) void epi_kernel(
    const float* __restrict__ ctx, const float* __restrict__ prev,
    const float* __restrict__ Wo, const float* __restrict__ bo,
    const float* __restrict__ g1, const float* __restrict__ b1ln,
    const float* __restrict__ W1, const float* __restrict__ b1,
    const float* __restrict__ W2, const float* __restrict__ b2,
    const float* __restrict__ g2, const float* __restrict__ b2ln,
    float* __restrict__ out) {
  __shared__ float WoT[64 * 65];
  __shared__ float W1T[64 * 65];
  __shared__ float W2T[64 * 65];
  __shared__ float cs[4][64];
  __shared__ float xs[4][64];
  __shared__ float hs[4][64];
  __shared__ float pA[8], pB[8];

  int tid = threadIdx.x;
  for (int idx = tid; idx < 4096; idx += 256) {
    int c = idx >> 6, d = idx & 63;
    WoT[d * 65 + c] = Wo[idx];
    W1T[d * 65 + c] = W1[idx];
    W2T[d * 65 + c] = W2[idx];
  }
  int c = tid & 63, s = tid >> 6;
  int lane = tid & 31, wid = tid >> 5;
  float boc = bo[c], g1c = g1[c], b1lc = b1ln[c], b1c = b1[c];
  float b2c = b2[c], g2c = g2[c], b2lc = b2ln[c];
  __syncthreads();

  for (int g = 0; g < 16; g++) {
    int row = blockIdx.x * 64 + g * 4 + s;
    cs[s][c] = ctx[(size_t)row * 64 + c];
    __syncthreads();

    float o = 0.f;
    #pragma unroll
    for (int d = 0; d < 64; d++) o = fmaf(cs[s][d], WoT[d * 65 + c], o);
    o += boc + prev[(size_t)row * 64 + c];

    // LN1 (row = 64 threads = warps 2s, 2s+1)
    float s1 = o, s2 = o * o;
    #pragma unroll
    for (int off = 16; off; off >>= 1) {
      s1 += __shfl_xor_sync(0xffffffffu, s1, off);
      s2 += __shfl_xor_sync(0xffffffffu, s2, off);
    }
    if (lane == 0) { pA[wid] = s1; pB[wid] = s2; }
    __syncthreads();
    float S1 = pA[s * 2] + pA[s * 2 + 1];
    float S2 = pB[s * 2] + pB[s * 2 + 1];
    float mu = S1 * (1.f / 64.f);
    float rstd = rsqrtf(S2 * (1.f / 64.f) - mu * mu + 1e-5f);
    float x = (o - mu) * rstd * g1c + b1lc;
    xs[s][c] = x;
    __syncthreads();

    float ha = 0.f;
    #pragma unroll
    for (int d = 0; d < 64; d++) ha = fmaf(xs[s][d], W1T[d * 65 + c], ha);
    float hv = fmaxf(ha + b1c, 0.f);
    hs[s][c] = hv;
    __syncthreads();

    float f = 0.f;
    #pragma unroll
    for (int d = 0; d < 64; d++) f = fmaf(hs[s][d], W2T[d * 65 + c], f);
    f += b2c + x;

    // LN2
    s1 = f; s2 = f * f;
    #pragma unroll
    for (int off = 16; off; off >>= 1) {
      s1 += __shfl_xor_sync(0xffffffffu, s1, off);
      s2 += __shfl_xor_sync(0xffffffffu, s2, off);
    }
    if (lane == 0) { pA[wid] = s1; pB[wid] = s2; }
    __syncthreads();
    S1 = pA[s * 2] + pA[s * 2 + 1];
    S2 = pB[s * 2] + pB[s * 2 + 1];
    mu = S1 * (1.f / 64.f);
    rstd = rsqrtf(S2 * (1.f / 64.f) - mu * mu + 1e-5f);
    out[(size_t)row * 64 + c] = (f - mu) * rstd * g2c + b2lc;
    __syncthreads();
  }
}

// ---------------------------------------------------------------------------
extern "C" void kernel_launch(void* const* d_in, const int* in_sizes, int n_in,
                              void* d_out, int out_size) {
  (void)n_in;
  const float* q    = (const float*)d_in[0];
  const float* k    = (const float*)d_in[1];
  const float* prev = (const float*)d_in[2];
  const float* Wq   = (const float*)d_in[3];
  const float* bq   = (const float*)d_in[4];
  const float* Wk   = (const float*)d_in[5];
  const float* bk   = (const float*)d_in[6];
  const float* Wv   = (const float*)d_in[7];
  const float* bv   = (const float*)d_in[8];
  const float* Wo   = (const float*)d_in[9];
  const float* bo   = (const float*)d_in[10];
  const float* g1   = (const float*)d_in[11];
  const float* b1l  = (const float*)d_in[12];
  const float* W1   = (const float*)d_in[13];
  const float* b1   = (const float*)d_in[14];
  const float* W2   = (const float*)d_in[15];
  const float* b2   = (const float*)d_in[16];
  const float* g2   = (const float*)d_in[17];
  const float* b2l  = (const float*)d_in[18];

  int B = in_sizes[0] / (LSEQ * EDIM);   // 64
  int nrows = B * LSEQ;                  // 32768
  float* out = (float*)d_out;
  float* attn_out = out + (size_t)nrows * EDIM;
  (void)out_size;

  float *qh, *kh, *vh, *ctx;
  cudaGetSymbolAddress((void**)&qh, g_qh);
  cudaGetSymbolAddress((void**)&kh, g_kh);
  cudaGetSymbolAddress((void**)&vh, g_vh);
  cudaGetSymbolAddress((void**)&ctx, g_ctx);

  proj_kernel<<<nrows / 16, 256>>>(q, Wq, bq, qh);
  proj_kernel<<<nrows / 16, 256>>>(k, Wk, bk, kh);
  proj_kernel<<<nrows / 16, 256>>>(k, Wv, bv, vh);

  int smem = (4096 + 4096 + 32 * 512) * 4;  // 98304 B
  cudaFuncSetAttribute(attn_kernel, cudaFuncAttributeMaxDynamicSharedMemorySize,
                       smem);
  attn_kernel<<<dim3(LSEQ / 32, B), 256, smem>>>(qh, kh, vh, ctx, attn_out);

  epi_kernel<<<nrows / 64, 256>>>(ctx, prev, Wo, bo, g1, b1l, W1, b1, W2, b2,
                                  g2, b2l, out);
}

// round 3
// speedup vs baseline: 1.0072x; 1.0072x over previous
#include <cuda_runtime.h>

// Shapes fixed by the problem: B=64, L=512, E=64, H=8, D=8
#define LSEQ 512
#define EDIM 64

// Scratch (static device globals — no allocation)
__device__ float g_qh[64 * 512 * 64];
__device__ float g_kh[64 * 512 * 64];
__device__ float g_vh[64 * 512 * 64];
__device__ float g_ctx[64 * 512 * 64];

// ---------------------------------------------------------------------------
// Warp-level helpers
// ---------------------------------------------------------------------------
__device__ __forceinline__ float warp_sum(float v) {
  #pragma unroll
  for (int off = 16; off; off >>= 1) v += __shfl_xor_sync(0xffffffffu, v, off);
  return v;
}

// matvec over a 64-row in float2-per-lane form: out[c] = sum_d x[d]*WT[d][c]
// WT layout: [64][66] (pad 2 keeps float2 loads 8B-aligned, near-conflict-free)
__device__ __forceinline__ float2 matvec64(const float* __restrict__ WT,
                                           float2 v, int lane) {
  float2 o = make_float2(0.f, 0.f);
  #pragma unroll
  for (int d = 0; d < 64; d++) {
    float xd = __shfl_sync(0xffffffffu, (d & 1) ? v.y : v.x, d >> 1);
    float2 w = *(const float2*)&WT[d * 66 + 2 * lane];
    o.x = fmaf(xd, w.x, o.x);
    o.y = fmaf(xd, w.y, o.y);
  }
  return o;
}

// ---------------------------------------------------------------------------
// Fused projections: out = x @ W.T + b for (q,Wq),(k,Wk),(k,Wv)
// blockIdx.y selects which. Warp-per-row, 8 rows per warp, no inner syncs.
// ---------------------------------------------------------------------------
__global__ __launch_bounds__(256) void proj_kernel(
    const float* __restrict__ q, const float* __restrict__ k,
    const float* __restrict__ Wq, const float* __restrict__ bq,
    const float* __restrict__ Wk, const float* __restrict__ bk,
    const float* __restrict__ Wv, const float* __restrict__ bv,
    float* __restrict__ qh, float* __restrict__ kh, float* __restrict__ vh) {
  __shared__ __align__(16) float WT[64 * 66];
  int sel = blockIdx.y;
  const float* x = (sel == 0) ? q : k;
  const float* W = (sel == 0) ? Wq : (sel == 1) ? Wk : Wv;
  const float* bias = (sel == 0) ? bq : (sel == 1) ? bk : bv;
  float* out = (sel == 0) ? qh : (sel == 1) ? kh : vh;

  int tid = threadIdx.x, lane = tid & 31, wid = tid >> 5;
  for (int idx = tid; idx < 4096; idx += 256) {
    int c = idx >> 6, d = idx & 63;
    WT[d * 66 + c] = W[idx];
  }
  float2 bc = *(const float2*)&bias[2 * lane];
  __syncthreads();

  int row0 = blockIdx.x * 64 + wid * 8;
  #pragma unroll 1
  for (int rr = 0; rr < 8; rr++) {
    int row = row0 + rr;
    float2 xv = ((const float2*)x)[(size_t)row * 32 + lane];
    float2 o = matvec64(WT, xv, lane);
    o.x += bc.x;
    o.y += bc.y;
    ((float2*)out)[(size_t)row * 32 + lane] = o;
  }
}

// ---------------------------------------------------------------------------
// Attention: block = (query-tile of 32, batch). 256 threads = 8 warps.
// Warp qg owns queries qg*4..qg*4+3 across ALL 512 keys (lane = key phase):
// softmax + ctx reductions are warp shuffles only. Head-mean attention
// accumulates in SMEM tile. launch_bounds(256,2) -> <=128 regs, 2 CTAs/SM.
// ---------------------------------------------------------------------------
__global__ __launch_bounds__(256, 2) void attn_kernel(
    const float* __restrict__ qh, const float* __restrict__ kh,
    const float* __restrict__ vh, float* __restrict__ ctx,
    float* __restrict__ attn_out) {
  extern __shared__ float sm[];
  float* Ks = sm;            // [8][512]
  float* Vs = sm + 4096;     // [8][512]
  float* Aacc = sm + 8192;   // [32][512]

  int b = blockIdx.y;
  int q0 = blockIdx.x * 32;
  int tid = threadIdx.x;
  int qg = tid >> 5;   // warp id = query group
  int ks = tid & 31;   // lane = key phase

  float4* A4 = (float4*)Aacc;
  for (int i = tid; i < 4096; i += 256) A4[i] = make_float4(0.f, 0.f, 0.f, 0.f);

  const float scale = 0.3535533905932738f;  // 1/sqrt(8)
  const float* kbase = kh + (size_t)b * 512 * 64;
  const float* vbase = vh + (size_t)b * 512 * 64;

  #pragma unroll 1
  for (int h = 0; h < 8; h++) {
    __syncthreads();  // prior head done with Ks/Vs
    #pragma unroll 2
    for (int idx = tid; idx < 4096; idx += 256) {
      int m = idx >> 3, d = idx & 7;
      int g = m * 64 + h * 8 + d;
      Ks[d * 512 + m] = kbase[g];
      Vs[d * 512 + m] = vbase[g];
    }
    __syncthreads();

    // scores: 4 queries x 16 key-chunks (key m = ks + 32*j)
    float s[4][16];
    {
      float qr[4][8];
      #pragma unroll
      for (int i = 0; i < 4; i++) {
        const float4* qp = (const float4*)(qh +
            ((size_t)(b * 512 + q0 + qg * 4 + i)) * 64 + h * 8);
        float4 a = qp[0], c4 = qp[1];
        qr[i][0] = a.x * scale; qr[i][1] = a.y * scale;
        qr[i][2] = a.z * scale; qr[i][3] = a.w * scale;
        qr[i][4] = c4.x * scale; qr[i][5] = c4.y * scale;
        qr[i][6] = c4.z * scale; qr[i][7] = c4.w * scale;
      }
      #pragma unroll
      for (int i = 0; i < 4; i++)
        #pragma unroll
        for (int j = 0; j < 16; j++) s[i][j] = 0.f;
      #pragma unroll
      for (int j = 0; j < 16; j++) {
        int m = ks + 32 * j;
        #pragma unroll
        for (int d = 0; d < 8; d++) {
          float kv = Ks[d * 512 + m];
          #pragma unroll
          for (int i = 0; i < 4; i++) s[i][j] = fmaf(qr[i][d], kv, s[i][j]);
        }
      }
    }

    // softmax over keys (warp-wide; lanes cover key space), exps kept in s
    float inv[4];
    #pragma unroll
    for (int i = 0; i < 4; i++) {
      float M = s[i][0];
      #pragma unroll
      for (int j = 1; j < 16; j++) M = fmaxf(M, s[i][j]);
      #pragma unroll
      for (int off = 16; off; off >>= 1)
        M = fmaxf(M, __shfl_xor_sync(0xffffffffu, M, off));
      float Z = 0.f;
      #pragma unroll
      for (int j = 0; j < 16; j++) {
        float e = __expf(s[i][j] - M);
        s[i][j] = e;
        Z += e;
      }
      Z = warp_sum(Z);
      inv[i] = 1.0f / Z;
    }

    // probabilities -> head-mean accum (SMEM) + ctx accum (regs, Vs reused 4x)
    float cacc[4][8];
    #pragma unroll
    for (int i = 0; i < 4; i++)
      #pragma unroll
      for (int d = 0; d < 8; d++) cacc[i][d] = 0.f;

    #pragma unroll
    for (int j = 0; j < 16; j++) {
      int m = ks + 32 * j;
      float p[4];
      #pragma unroll
      for (int i = 0; i < 4; i++) {
        p[i] = s[i][j] * inv[i];
        Aacc[(qg * 4 + i) * 512 + m] += 0.125f * p[i];  // head mean
      }
      #pragma unroll
      for (int d = 0; d < 8; d++) {
        float v = Vs[d * 512 + m];
        #pragma unroll
        for (int i = 0; i < 4; i++) cacc[i][d] = fmaf(p[i], v, cacc[i][d]);
      }
    }

    // warp-reduce ctx partials; every lane ends with all 32 totals
    #pragma unroll
    for (int i = 0; i < 4; i++)
      #pragma unroll
      for (int d = 0; d < 8; d++)
        #pragma unroll
        for (int off = 16; off; off >>= 1)
          cacc[i][d] += __shfl_xor_sync(0xffffffffu, cacc[i][d], off);

    // lane ks writes entry (i = ks>>3, d = ks&7) — static select chain
    int li = ks >> 3, ld = ks & 7;
    float val = 0.f;
    #pragma unroll
    for (int i = 0; i < 4; i++)
      #pragma unroll
      for (int d = 0; d < 8; d++)
        if (li == i && ld == d) val = cacc[i][d];
    ctx[((size_t)(b * 512 + q0 + qg * 4 + li)) * 64 + h * 8 + ld] = val;
  }

  __syncthreads();
  // write head-averaged attention, coalesced float4
  float4* ao4 = (float4*)(attn_out + ((size_t)b * 512 + q0) * 512);
  for (int idx = tid; idx < 4096; idx += 256) ao4[idx] = A4[idx];
}

// ---------------------------------------------------------------------------
// Epilogue: warp-per-row, no block syncs in the row loop.
// o = ctx@Wo.T + bo + prev; x = LN1(o);
// f = relu(x@W1.T+b1)@W2.T + b2 + x; out = LN2(f)
// ---------------------------------------------------------------------------
__global__ __launch_bounds__(256) void epi_kernel(
    const float* __restrict__ ctx, const float* __restrict__ prev,
    const float* __restrict__ Wo, const float* __restrict__ bo,
    const float* __restrict__ g1, const float* __restrict__ b1ln,
    const float* __restrict__ W1, const float* __restrict__ b1,
    const float* __restrict__ W2, const float* __restrict__ b2,
    const float* __restrict__ g2, const float* __restrict__ b2ln,
    float* __restrict__ out) {
  __shared__ __align__(16) float WoT[64 * 66];
  __shared__ __align__(16) float W1T[64 * 66];
  __shared__ __align__(16) float W2T[64 * 66];

  int tid = threadIdx.x, lane = tid & 31, wid = tid >> 5;
  for (int idx = tid; idx < 4096; idx += 256) {
    int c = idx >> 6, d = idx & 63;
    WoT[d * 66 + c] = Wo[idx];
    W1T[d * 66 + c] = W1[idx];
    W2T[d * 66 + c] = W2[idx];
  }
  float2 boc = *(const float2*)&bo[2 * lane];
  float2 g1c = *(const float2*)&g1[2 * lane];
  float2 b1lc = *(const float2*)&b1ln[2 * lane];
  float2 b1c = *(const float2*)&b1[2 * lane];
  float2 b2c = *(const float2*)&b2[2 * lane];
  float2 g2c = *(const float2*)&g2[2 * lane];
  float2 b2lc = *(const float2*)&b2ln[2 * lane];
  __syncthreads();

  int row0 = blockIdx.x * 64 + wid * 8;
  #pragma unroll 1
  for (int rr = 0; rr < 8; rr++) {
    int row = row0 + rr;
    float2 cv = ((const float2*)ctx)[(size_t)row * 32 + lane];
    float2 o = matvec64(WoT, cv, lane);
    float2 pv = ((const float2*)prev)[(size_t)row * 32 + lane];
    o.x += boc.x + pv.x;
    o.y += boc.y + pv.y;

    // LN1 (warp-local over 64 values)
    float S1 = warp_sum(o.x + o.y);
    float S2 = warp_sum(o.x * o.x + o.y * o.y);
    float mu = S1 * (1.f / 64.f);
    float rstd = rsqrtf(S2 * (1.f / 64.f) - mu * mu + 1e-5f);
    float2 x;
    x.x = (o.x - mu) * rstd * g1c.x + b1lc.x;
    x.y = (o.y - mu) * rstd * g1c.y + b1lc.y;

    // hidden = relu(x @ W1.T + b1)
    float2 hv = matvec64(W1T, x, lane);
    hv.x = fmaxf(hv.x + b1c.x, 0.f);
    hv.y = fmaxf(hv.y + b1c.y, 0.f);

    // f = hidden @ W2.T + b2 + x
    float2 f = matvec64(W2T, hv, lane);
    f.x += b2c.x + x.x;
    f.y += b2c.y + x.y;

    // LN2
    S1 = warp_sum(f.x + f.y);
    S2 = warp_sum(f.x * f.x + f.y * f.y);
    mu = S1 * (1.f / 64.f);
    rstd = rsqrtf(S2 * (1.f / 64.f) - mu * mu + 1e-5f);
    float2 res;
    res.x = (f.x - mu) * rstd * g2c.x + b2lc.x;
    res.y = (f.y - mu) * rstd * g2c.y + b2lc.y;
    ((float2*)out)[(size_t)row * 32 + lane] = res;
  }
}

// ---------------------------------------------------------------------------
extern "C" void kernel_launch(void* const* d_in, const int* in_sizes, int n_in,
                              void* d_out, int out_size) {
  (void)n_in;
  const float* q    = (const float*)d_in[0];
  const float* k    = (const float*)d_in[1];
  const float* prev = (const float*)d_in[2];
  const float* Wq   = (const float*)d_in[3];
  const float* bq   = (const float*)d_in[4];
  const float* Wk   = (const float*)d_in[5];
  const float* bk   = (const float*)d_in[6];
  const float* Wv   = (const float*)d_in[7];
  const float* bv   = (const float*)d_in[8];
  const float* Wo   = (const float*)d_in[9];
  const float* bo   = (const float*)d_in[10];
  const float* g1   = (const float*)d_in[11];
  const float* b1l  = (const float*)d_in[12];
  const float* W1   = (const float*)d_in[13];
  const float* b1   = (const float*)d_in[14];
  const float* W2   = (const float*)d_in[15];
  const float* b2   = (const float*)d_in[16];
  const float* g2   = (const float*)d_in[17];
  const float* b2l  = (const float*)d_in[18];

  int B = in_sizes[0] / (LSEQ * EDIM);   // 64
  int nrows = B * LSEQ;                  // 32768
  float* out = (float*)d_out;
  float* attn_out = out + (size_t)nrows * EDIM;
  (void)out_size;

  float *qh, *kh, *vh, *ctx;
  cudaGetSymbolAddress((void**)&qh, g_qh);
  cudaGetSymbolAddress((void**)&kh, g_kh);
  cudaGetSymbolAddress((void**)&vh, g_vh);
  cudaGetSymbolAddress((void**)&ctx, g_ctx);

  proj_kernel<<<dim3(nrows / 64, 3), 256>>>(q, k, Wq, bq, Wk, bk, Wv, bv,
                                            qh, kh, vh);

  int smem = (4096 + 4096 + 32 * 512) * 4;  // 98304 B
  cudaFuncSetAttribute(attn_kernel, cudaFuncAttributeMaxDynamicSharedMemorySize,
                       smem);
  attn_kernel<<<dim3(LSEQ / 32, B), 256, smem>>>(qh, kh, vh, ctx, attn_out);

  epi_kernel<<<nrows / 64, 256>>>(ctx, prev, Wo, bo, g1, b1l, W1, b1, W2, b2,
                                  g2, b2l, out);
}